// round 2
// baseline (speedup 1.0000x reference)
#include <cuda_runtime.h>

// y[i,o,n] = sum_j sum_k x[j,(o-1)%28, n+k-1]*W[i,j,0,k]
//                      + x[j,(o-2)%28, n+k-1]*W[i,j,1,k]
// x: (64,28,28) f32, W: (128,64,2,3) f32, y: (128,28,28) f32, zero-pad over n.
//
// Block: 8 channels (i) x 4 rows (o) x 28 cols (n), half of j (32).
// Grid (16, 7, 2) = 224 blocks, 128 threads each.
// Thread tile: 2 i x 4 n  (warp w owns i_local {2w,2w+1}; lane -> (ol, ng)).
// j-split partials combined via atomicAdd after cudaMemsetAsync(out, 0).

__global__ __launch_bounds__(128, 8)
void conv_shift_kernel(const float* __restrict__ x,
                       const float* __restrict__ W,
                       float* __restrict__ out) {
    // x rows staged padded: index p = n+1, p=0..29 (30 used, stride 34 to de-phase banks)
    __shared__ __align__(16) float xs[32][6][34];
    // weights: [j][i_local][ l*4 + k ], float4-loadable; slots 3,7 are pad
    __shared__ __align__(16) float ws[32][8][8];

    const int tid = threadIdx.x;
    const int ib = blockIdx.x * 8;   // channel base (0..120)
    const int ob = blockIdx.y * 4;   // o base (0..24)
    const int jb = blockIdx.z * 32;  // j base (0 or 32)

    // Zero the n-pad columns
    for (int idx = tid; idx < 32 * 6; idx += 128) {
        int jl = idx / 6, rl = idx - jl * 6;
        xs[jl][rl][0]  = 0.0f;
        xs[jl][rl][29] = 0.0f;
    }
    // Stage x rows: row_local rl corresponds to global row (ob - 2 + rl) mod 28
    for (int idx = tid; idx < 32 * 6 * 28; idx += 128) {
        int jl  = idx / 168;
        int rem = idx - jl * 168;
        int rl  = rem / 28;
        int n   = rem - rl * 28;
        int row = ob - 2 + rl;
        row = (row + 28) % 28;
        xs[jl][rl][n + 1] = x[(jb + jl) * 784 + row * 28 + n];
    }
    // Stage weights
    for (int idx = tid; idx < 32 * 8 * 6; idx += 128) {
        int jl  = idx / 48;
        int rem = idx - jl * 48;
        int il  = rem / 6;
        int q   = rem - il * 6;
        int l   = q / 3;
        int k   = q - l * 3;
        ws[jl][il][l * 4 + k] = W[(ib + il) * 384 + (jb + jl) * 6 + l * 3 + k];
    }
    __syncthreads();

    const int warp = tid >> 5;
    const int lane = tid & 31;
    const int ol = lane / 7;   // 0..3 (lanes 28..31 -> 4, redundant compute, masked at store)
    const int ng = lane % 7;   // 0..6 -> n0 = 4*ng
    const int il0 = warp * 2;
    const int il1 = il0 + 1;

    float acc0[4] = {0.f, 0.f, 0.f, 0.f};
    float acc1[4] = {0.f, 0.f, 0.f, 0.f};

    const int n0 = 4 * ng;

    #pragma unroll 4
    for (int jl = 0; jl < 32; jl++) {
        const float4 a0 = *reinterpret_cast<const float4*>(&ws[jl][il0][0]); // i0, l=0 (applies to row o-1)
        const float4 a1 = *reinterpret_cast<const float4*>(&ws[jl][il0][4]); // i0, l=1 (applies to row o-2)
        const float4 b0 = *reinterpret_cast<const float4*>(&ws[jl][il1][0]);
        const float4 b1 = *reinterpret_cast<const float4*>(&ws[jl][il1][4]);

        const float* p1 = &xs[jl][ol + 1][n0]; // row (o-1): padded taps n0 .. n0+5
        const float* p2 = &xs[jl][ol][n0];     // row (o-2)

        float v1[6], v2[6];
        #pragma unroll
        for (int t = 0; t < 3; t++) {
            float2 u1 = *reinterpret_cast<const float2*>(p1 + 2 * t);
            float2 u2 = *reinterpret_cast<const float2*>(p2 + 2 * t);
            v1[2 * t] = u1.x; v1[2 * t + 1] = u1.y;
            v2[2 * t] = u2.x; v2[2 * t + 1] = u2.y;
        }

        const float wa0[3] = {a0.x, a0.y, a0.z};
        const float wa1[3] = {a1.x, a1.y, a1.z};
        const float wb0[3] = {b0.x, b0.y, b0.z};
        const float wb1[3] = {b1.x, b1.y, b1.z};

        #pragma unroll
        for (int n = 0; n < 4; n++) {
            #pragma unroll
            for (int k = 0; k < 3; k++) {
                acc0[n] = fmaf(v1[n + k], wa0[k], acc0[n]);
                acc0[n] = fmaf(v2[n + k], wa1[k], acc0[n]);
                acc1[n] = fmaf(v1[n + k], wb0[k], acc1[n]);
                acc1[n] = fmaf(v2[n + k], wb1[k], acc1[n]);
            }
        }
    }

    if (lane < 28) {
        const int o = ob + ol;
        float* d0 = out + (ib + il0) * 784 + o * 28 + n0;
        float* d1 = out + (ib + il1) * 784 + o * 28 + n0;
        #pragma unroll
        for (int n = 0; n < 4; n++) {
            atomicAdd(&d0[n], acc0[n]);
            atomicAdd(&d1[n], acc1[n]);
        }
    }
}

extern "C" void kernel_launch(void* const* d_in, const int* in_sizes, int n_in,
                              void* d_out, int out_size) {
    const float* x = (const float*)d_in[0];  // (1,64,28,28)  = 50176 f32
    const float* W = (const float*)d_in[1];  // (128,64,2,3) = 147456 f32
    float* out = (float*)d_out;              // (1,128,28,28) = 100352 f32

    cudaMemsetAsync(out, 0, (size_t)out_size * sizeof(float));

    dim3 grid(16, 7, 2);  // (i-groups of 8, o-groups of 4, j halves of 32)
    conv_shift_kernel<<<grid, 128>>>(x, W, out);
}

// round 3
// speedup vs baseline: 1.3208x; 1.3208x over previous
#include <cuda_runtime.h>

// y[i,o,n] = sum_j sum_k x[j,(o-1)%28, n+k-1]*W[i,j,0,k]
//                      + x[j,(o-2)%28, n+k-1]*W[i,j,1,k]
// x: (64,28,28) f32, W: (128,64,2,3) f32, y: (128,28,28) f32, zero-pad over n.
//
// Block: 16 channels (i) x 4 rows (o) x 28 cols (n), 8 j-channels.
// Grid (8, 7, 8) = 448 blocks, 128 threads -> ~12 warps/SM.
// Thread tile: 4 i x 4 n (warp w owns i_local {4w..4w+3}; lane -> (ol, ng)).
// j-split partials combined via atomicAdd after cudaMemsetAsync(out, 0).

#define JT 8   // j per block

__global__ __launch_bounds__(128, 8)
void conv_shift_kernel(const float* __restrict__ x,
                       const float* __restrict__ W,
                       float* __restrict__ out) {
    // x rows staged padded: padded index p = n+1, p=0..29 (stride 34 de-phases banks)
    __shared__ __align__(16) float xs[JT][6][34];
    // weights: [j][i_local][ l*4 + k ], float4-loadable; slots 3,7 are pad
    __shared__ __align__(16) float ws[JT][16][8];

    const int tid = threadIdx.x;
    const int ib = blockIdx.x * 16;  // channel base (0..112)
    const int ob = blockIdx.y * 4;   // o base (0..24)
    const int jb = blockIdx.z * JT;  // j base

    // Zero the n-pad columns
    if (tid < JT * 6) {
        int jl = tid / 6, rl = tid - jl * 6;
        xs[jl][rl][0]  = 0.0f;
        xs[jl][rl][29] = 0.0f;
    }
    // Stage x rows: row_local rl = global row (ob - 2 + rl) mod 28
    for (int idx = tid; idx < JT * 6 * 28; idx += 128) {
        int jl  = idx / 168;
        int rem = idx - jl * 168;
        int rl  = rem / 28;
        int n   = rem - rl * 28;
        int row = ob - 2 + rl;
        row = (row + 28) % 28;
        xs[jl][rl][n + 1] = x[(jb + jl) * 784 + row * 28 + n];
    }
    // Stage weights
    for (int idx = tid; idx < JT * 16 * 6; idx += 128) {
        int jl  = idx / 96;
        int rem = idx - jl * 96;
        int il  = rem / 6;
        int q   = rem - il * 6;
        int l   = q / 3;
        int k   = q - l * 3;
        ws[jl][il][l * 4 + k] = W[(ib + il) * 384 + (jb + jl) * 6 + l * 3 + k];
    }
    __syncthreads();

    const int warp = tid >> 5;
    const int lane = tid & 31;
    const int ol = lane / 7;   // 0..3 (lanes 28..31 compute redundantly, masked at store)
    const int ng = lane % 7;   // 0..6 -> n0 = 4*ng
    const int il0 = warp * 4;
    const int n0 = 4 * ng;

    float acc[4][4];
    #pragma unroll
    for (int c = 0; c < 4; c++)
        #pragma unroll
        for (int n = 0; n < 4; n++) acc[c][n] = 0.0f;

    #pragma unroll 2
    for (int jl = 0; jl < JT; jl++) {
        // x taps for rows (o-1) and (o-2): padded indices n0 .. n0+5
        const float* p1 = &xs[jl][ol + 1][n0];
        const float* p2 = &xs[jl][ol][n0];

        float v1[6], v2[6];
        #pragma unroll
        for (int t = 0; t < 3; t++) {
            float2 u1 = *reinterpret_cast<const float2*>(p1 + 2 * t);
            float2 u2 = *reinterpret_cast<const float2*>(p2 + 2 * t);
            v1[2 * t] = u1.x; v1[2 * t + 1] = u1.y;
            v2[2 * t] = u2.x; v2[2 * t + 1] = u2.y;
        }

        #pragma unroll
        for (int c = 0; c < 4; c++) {
            const float4 a0 = *reinterpret_cast<const float4*>(&ws[jl][il0 + c][0]); // l=0 (row o-1)
            const float4 a1 = *reinterpret_cast<const float4*>(&ws[jl][il0 + c][4]); // l=1 (row o-2)
            const float wa0[3] = {a0.x, a0.y, a0.z};
            const float wa1[3] = {a1.x, a1.y, a1.z};
            #pragma unroll
            for (int n = 0; n < 4; n++) {
                #pragma unroll
                for (int k = 0; k < 3; k++) {
                    acc[c][n] = fmaf(v1[n + k], wa0[k], acc[c][n]);
                    acc[c][n] = fmaf(v2[n + k], wa1[k], acc[c][n]);
                }
            }
        }
    }

    if (lane < 28) {
        const int o = ob + ol;
        #pragma unroll
        for (int c = 0; c < 4; c++) {
            float* d = out + (ib + il0 + c) * 784 + o * 28 + n0;
            #pragma unroll
            for (int n = 0; n < 4; n++) {
                atomicAdd(&d[n], acc[c][n]);
            }
        }
    }
}

extern "C" void kernel_launch(void* const* d_in, const int* in_sizes, int n_in,
                              void* d_out, int out_size) {
    const float* x = (const float*)d_in[0];  // (1,64,28,28)  = 50176 f32
    const float* W = (const float*)d_in[1];  // (128,64,2,3) = 147456 f32
    float* out = (float*)d_out;              // (1,128,28,28) = 100352 f32

    cudaMemsetAsync(out, 0, (size_t)out_size * sizeof(float));

    dim3 grid(8, 7, 8);  // (i-groups of 16, o-groups of 4, j-groups of 8)
    conv_shift_kernel<<<grid, 128>>>(x, W, out);
}